// round 13
// baseline (speedup 1.0000x reference)
#include <cuda_runtime.h>
#include <math.h>

// Shapes (fixed by the problem)
#define BB  2
#define NN  512
#define HID 128
#define DD  32    // Chebyshev orders; measured: truncation below fp32 noise at 32

#define KSPL  4                      // prologue k-dimension split
#define NODES 4                      // nodes per prologue block
#define PRO_BLOCKS (DD / NODES)      // 8
#define MAIN_BLOCKS ((BB * NN) / 4)  // 256 (4 rows per block)
#define TOTAL_BLOCKS (PRO_BLOCKS + MAIN_BLOCKS)  // 264 <= 2*148 co-resident

// Scratch (static device globals; no allocation)
__device__ float g_inv_hd;           // 2 / dmax
__device__ float g_G[DD * HID];      // network(+Wo) at Chebyshev nodes
__device__ float g_C[DD * HID];      // Chebyshev coefficients
__device__ unsigned g_flag_dmax;     // 1 when g_inv_hd ready
__device__ unsigned g_arrive;        // prologue-internal 8-block barrier
__device__ unsigned g_done;          // prologue blocks finished (g_C ready at 8)
__device__ unsigned g_fin;           // main blocks finished; last resets all

union SmemU {
    struct {
        float red[512];
        float buf[NODES][HID];          // activations
        float part[KSPL][NODES][HID];   // per-quarter partials
        float costab[NODES][DD];
        float sG[DD][HID];              // staged G (16KB)
    } pro;
    struct {
        float sx[NN * 2];
        float sred[16][DD];
        float sredc[4][DD];
    } mn;
};

__global__ __launch_bounds__(512, 2) void fused_kernel(
    const float* __restrict__ x,
    const float* __restrict__ W10, const float* __restrict__ b10,
    const float* __restrict__ W20, const float* __restrict__ b20,
    const float* __restrict__ W11, const float* __restrict__ b11,
    const float* __restrict__ W21, const float* __restrict__ b21,
    const float* __restrict__ W12, const float* __restrict__ b12,
    const float* __restrict__ W22, const float* __restrict__ b22,
    const float* __restrict__ Wo,  const float* __restrict__ bo,
    float* __restrict__ out)
{
    __shared__ SmemU sm;
    const int tid = threadIdx.x;

    if (blockIdx.x < PRO_BLOCKS) {
        // ===================== PROLOGUE PATH (fast KSPL design) =====================
        const int c  = tid & (HID - 1);
        const int q  = tid >> 7;               // 0..3
        const int k0 = q * (HID / KSPL);       // 32 k's per quarter

        const float* Ws[6] = {W20, W11, W21, W12, W22, Wo};
        const float* bs[6] = {b20, b11, b21, b12, b22, (const float*)0};

        // issue layer-0 weight loads early
        float wc[HID / KSPL];
        #pragma unroll
        for (int kk = 0; kk < HID / KSPL; kk++) wc[kk] = Ws[0][(k0 + kk) * HID + c];

        // dmax = 2*max||x|| (triangle-inequality bound), deterministic
        float mx = 0.0f;
        for (int t = tid; t < BB * NN; t += 512) {
            float a = x[2 * t], b = x[2 * t + 1];
            mx = fmaxf(mx, fmaf(a, a, b * b));
        }
        sm.pro.red[tid] = mx;
        __syncthreads();
        #pragma unroll
        for (int s = 256; s > 0; s >>= 1) {
            if (tid < s) sm.pro.red[tid] = fmaxf(sm.pro.red[tid], sm.pro.red[tid + s]);
            __syncthreads();
        }
        const float dmax = 2.0f * sqrtf(sm.pro.red[0]) * 1.000001f + 1e-6f;
        if (blockIdx.x == 0 && tid == 0) {
            g_inv_hd = 2.0f / dmax;
            __threadfence();
            atomicExch(&g_flag_dmax, 1u);      // release to main blocks
        }

        // layer 0 (scalar input): thread-set q computes node q of this block
        {
            int mnode = blockIdx.x * NODES + q;
            float d = 0.5f * (cospif((mnode + 0.5f) * (1.0f / DD)) + 1.0f) * dmax;
            float a = fmaf(d, W10[c], b10[c]);
            sm.pro.buf[q][c] = a / (1.0f + expf(-a));
        }
        __syncthreads();

        #pragma unroll
        for (int l = 0; l < 6; l++) {
            float wn[HID / KSPL];
            if (l < 5) {
                #pragma unroll
                for (int kk = 0; kk < HID / KSPL; kk++)
                    wn[kk] = Ws[l + 1][(k0 + kk) * HID + c];
            }
            float h0 = 0.0f, h1 = 0.0f, h2 = 0.0f, h3 = 0.0f;
            #pragma unroll
            for (int kk = 0; kk < HID / KSPL; kk++) {
                const int k = k0 + kk;
                const float w = wc[kk];
                h0 = fmaf(sm.pro.buf[0][k], w, h0);
                h1 = fmaf(sm.pro.buf[1][k], w, h1);
                h2 = fmaf(sm.pro.buf[2][k], w, h2);
                h3 = fmaf(sm.pro.buf[3][k], w, h3);
            }
            sm.pro.part[q][0][c] = h0;
            sm.pro.part[q][1][c] = h1;
            sm.pro.part[q][2][c] = h2;
            sm.pro.part[q][3][c] = h3;
            __syncthreads();
            float v = (bs[l] ? bs[l][c] : 0.0f) +
                      ((sm.pro.part[0][q][c] + sm.pro.part[1][q][c]) +
                       (sm.pro.part[2][q][c] + sm.pro.part[3][q][c]));
            if (l == 1 || l == 3) v = v / (1.0f + expf(-v));   // silu
            if (l < 5) sm.pro.buf[q][c] = v;                   // reads done pre-sync
            else g_G[(blockIdx.x * NODES + q) * HID + c] = v;
            __syncthreads();
            #pragma unroll
            for (int kk = 0; kk < HID / KSPL; kk++) wc[kk] = wn[kk];
        }

        // barrier across the 8 prologue blocks (G complete)
        __threadfence();
        if (tid == 0) {
            atomicAdd(&g_arrive, 1u);
            while (*(volatile unsigned*)&g_arrive < (unsigned)PRO_BLOCKS) __nanosleep(32);
        }
        __syncthreads();
        __threadfence();

        // DCT-II: block produces coefficient rows k = blockIdx*4 + q
        for (int t = tid; t < NODES * DD; t += 512) {
            int qq = t / DD, m = t - qq * DD;
            int k = blockIdx.x * NODES + qq;
            int num = (k * (2 * m + 1)) & (4 * DD - 1);   // cospi period 2
            sm.pro.costab[qq][m] = cospif((float)num * (1.0f / (2.0f * DD)));
        }
        for (int t = tid; t < DD * HID / 4; t += 512)
            reinterpret_cast<float4*>(sm.pro.sG)[t] =
                __ldcg(reinterpret_cast<const float4*>(g_G) + t);
        __syncthreads();

        {
            int k = blockIdx.x * NODES + q;
            float acc = 0.0f;
            #pragma unroll
            for (int m = 0; m < DD; m++)
                acc = fmaf(sm.pro.costab[q][m], sm.pro.sG[m][c], acc);
            float wgt = (k == 0) ? (1.0f / DD) : (2.0f / DD);
            g_C[k * HID + c] = acc * wgt;
        }
        __threadfence();
        __syncthreads();
        if (tid == 0) atomicAdd(&g_done, 1u);   // release coefficients
        return;
    }

    // ===================== MAIN PATH (runs concurrently) =====================
    const int mb = blockIdx.x - PRO_BLOCKS;     // 0..255
    const int b  = mb >> 7;                     // 128 blocks per batch

    // stage x via float4 (overlaps the dmax wait)
    for (int t = tid; t < NN * 2 / 4; t += 512)
        reinterpret_cast<float4*>(sm.mn.sx)[t] =
            reinterpret_cast<const float4*>(x + b * NN * 2)[t];

    if (tid == 0) {
        while (*(volatile unsigned*)&g_flag_dmax == 0u) __nanosleep(32);
    }
    __syncthreads();        // orders sx stores AND the flag acquire
    __threadfence();
    const float inv_hd = *(volatile float*)&g_inv_hd;

    const int w    = tid >> 5;                  // warp 0..15
    const int lane = tid & 31;
    const int r    = w >> 2;                    // row-in-block 0..3
    const int h    = w & 3;                     // j-quarter 0..3
    const int i    = ((mb & 127) << 2) + r;     // row within batch
    const float xi0 = sm.mn.sx[2 * i], xi1 = sm.mn.sx[2 * i + 1];

    float s[DD];
    {
        const int j0 = h * 128;
        const int ja = j0 + lane, jb = ja + 32, jc = ja + 64, jd = ja + 96;
        float dxa = xi0 - sm.mn.sx[2 * ja], dya = xi1 - sm.mn.sx[2 * ja + 1];
        float dxb = xi0 - sm.mn.sx[2 * jb], dyb = xi1 - sm.mn.sx[2 * jb + 1];
        float dxc = xi0 - sm.mn.sx[2 * jc], dyc = xi1 - sm.mn.sx[2 * jc + 1];
        float dxd = xi0 - sm.mn.sx[2 * jd], dyd = xi1 - sm.mn.sx[2 * jd + 1];
        float za = fmaf(sqrtf(fmaf(dxa, dxa, dya * dya)), inv_hd, -1.0f);
        float zb = fmaf(sqrtf(fmaf(dxb, dxb, dyb * dyb)), inv_hd, -1.0f);
        float zc = fmaf(sqrtf(fmaf(dxc, dxc, dyc * dyc)), inv_hd, -1.0f);
        float zd = fmaf(sqrtf(fmaf(dxd, dxd, dyd * dyd)), inv_hd, -1.0f);
        za = fminf(fmaxf(za, -1.0f), 1.0f);
        zb = fminf(fmaxf(zb, -1.0f), 1.0f);
        zc = fminf(fmaxf(zc, -1.0f), 1.0f);
        zd = fminf(fmaxf(zd, -1.0f), 1.0f);

        s[0] = 4.0f;                            // T_0 == 1, 4 j's per lane
        s[1] = (za + zb) + (zc + zd);
        float t0a = 1.0f, t1a = za, z2a = za + za;
        float t0b = 1.0f, t1b = zb, z2b = zb + zb;
        float t0c = 1.0f, t1c = zc, z2c = zc + zc;
        float t0d = 1.0f, t1d = zd, z2d = zd + zd;
        #pragma unroll
        for (int k = 2; k < DD; k++) {
            float ta = fmaf(z2a, t1a, -t0a); t0a = t1a; t1a = ta;
            float tb = fmaf(z2b, t1b, -t0b); t0b = t1b; t1b = tb;
            float tc = fmaf(z2c, t1c, -t0c); t0c = t1c; t1c = tc;
            float td = fmaf(z2d, t1d, -t0d); t0d = t1d; t1d = td;
            s[k] = (ta + tb) + (tc + td);
        }
    }

    // reduce-scatter butterfly: lane ends holding k = lane
    #pragma unroll
    for (int st = 0; st < 5; st++) {
        const int off = 16 >> st;
        const int len = 16 >> st;
        const bool hi = (lane & off) != 0;
        #pragma unroll
        for (int k = 0; k < len; k++) {
            float send = hi ? s[k] : s[k + len];
            float recv = __shfl_xor_sync(0xffffffffu, send, off);
            s[k] = (hi ? s[k + len] : s[k]) + recv;
        }
    }
    sm.mn.sred[w][lane] = s[0];
    __syncthreads();

    // combine the 4 j-quarters per row (deterministic sequential order)
    if (tid < 4 * DD) {
        const int rr = tid >> 5, kk = tid & 31;
        sm.mn.sredc[rr][kk] = ((sm.mn.sred[4 * rr][kk]     + sm.mn.sred[4 * rr + 1][kk])
                             + (sm.mn.sred[4 * rr + 2][kk] + sm.mn.sred[4 * rr + 3][kk]))
                              * (1.0f / (float)NN);
    }

    // wait for coefficients (prologue ran concurrently)
    if (tid == 0) {
        while (*(volatile unsigned*)&g_done < (unsigned)PRO_BLOCKS) __nanosleep(32);
    }
    __syncthreads();        // orders sredc stores AND the g_done acquire
    __threadfence();

    // contract with C: warp owns 32 columns, lane owns 1 (coalesced, L1-bypass)
    const int c0 = h * 32 + lane;
    float acc = bo[c0];
    #pragma unroll
    for (int k = 0; k < DD; k++)
        acc = fmaf(sm.mn.sredc[r][k], __ldcg(&g_C[k * HID + c0]), acc);
    const int gi = b * NN + i;
    out[gi * HID + c0] = acc;

    // replay-safe reset: last main block restores all counters to 0
    __threadfence();
    __syncthreads();
    if (tid == 0) {
        unsigned old = atomicAdd(&g_fin, 1u);
        if (old == (unsigned)(MAIN_BLOCKS - 1)) {
            g_flag_dmax = 0u;
            g_arrive    = 0u;
            g_done      = 0u;
            g_fin       = 0u;
            __threadfence();
        }
    }
}

// ---------------------------------------------------------------------------
// Launch: ONE graph-capturable kernel; prologue (8 blocks) and main (256
// blocks) run concurrently, synchronized by device flags; all counters are
// restored to 0 before exit on every launch (bitwise replay-safe).
// Input order: x, W1_0,b1_0,W2_0,b2_0, W1_1,b1_1,W2_1,b2_1, W1_2,b1_2,W2_2,b2_2, Wo,bo
// ---------------------------------------------------------------------------
extern "C" void kernel_launch(void* const* d_in, const int* in_sizes, int n_in,
                              void* d_out, int out_size)
{
    const float* x   = (const float*)d_in[0];
    const float* W10 = (const float*)d_in[1];
    const float* b10 = (const float*)d_in[2];
    const float* W20 = (const float*)d_in[3];
    const float* b20 = (const float*)d_in[4];
    const float* W11 = (const float*)d_in[5];
    const float* b11 = (const float*)d_in[6];
    const float* W21 = (const float*)d_in[7];
    const float* b21 = (const float*)d_in[8];
    const float* W12 = (const float*)d_in[9];
    const float* b12 = (const float*)d_in[10];
    const float* W22 = (const float*)d_in[11];
    const float* b22 = (const float*)d_in[12];
    const float* Wo  = (const float*)d_in[13];
    const float* bo  = (const float*)d_in[14];
    float* out = (float*)d_out;

    fused_kernel<<<TOTAL_BLOCKS, 512>>>(x, W10, b10, W20, b20, W11, b11,
                                        W21, b21, W12, b12, W22, b22, Wo, bo, out);
}

// round 14
// speedup vs baseline: 1.1997x; 1.1997x over previous
#include <cuda_runtime.h>
#include <math.h>

// Shapes (fixed by the problem)
#define BB  2
#define NN  512
#define HID 128
#define DD  32    // Chebyshev orders; measured: truncation below fp32 noise at 32

// prologue tiling: 16 blocks x 512 thr, 2 nodes/block, k split 4 ways
#define NODES 2
#define KSPL  4
#define NE_BLOCKS (DD / NODES)     // 16
#define NE_THREADS 512

// Scratch (static device globals; no allocation)
__device__ float g_inv_hd;        // 2 / dmax
__device__ float g_G[DD * HID];   // network(+Wo) at Chebyshev nodes
__device__ float g_C[DD * HID];   // Chebyshev coefficients
__device__ unsigned g_arrive;     // grid barrier counter (0 at start AND end of every launch)

// ---------------------------------------------------------------------------
// Prologue: phase 1 = exact fp32 network at DD Chebyshev nodes (+Wo fold),
// phase 2 (after 16-block grid barrier) = DCT-II -> coefficients.
// Thread (q,c): q = k-quarter (32 k's), c = output column. 2 nodes per block.
// Per thread per layer: 32 LDG (weights, prefetched), 16 LDS.128 (buf), 64 FMA.
// ---------------------------------------------------------------------------
__global__ __launch_bounds__(NE_THREADS) void prologue_kernel(
    const float* __restrict__ x,
    const float* __restrict__ W10, const float* __restrict__ b10,
    const float* __restrict__ W20, const float* __restrict__ b20,
    const float* __restrict__ W11, const float* __restrict__ b11,
    const float* __restrict__ W21, const float* __restrict__ b21,
    const float* __restrict__ W12, const float* __restrict__ b12,
    const float* __restrict__ W22, const float* __restrict__ b22,
    const float* __restrict__ Wo)
{
    __shared__ float red[NE_THREADS];
    __shared__ __align__(16) float buf[NODES][HID];   // activations
    __shared__ float part[KSPL][NODES][HID];          // per-quarter partials
    __shared__ float costab[NODES][DD];               // phase 2: cos table
    __shared__ __align__(16) float sG[DD][HID];       // phase 2: staged G (16KB)

    const int c  = threadIdx.x & (HID - 1);
    const int q  = threadIdx.x >> 7;           // 0..3
    const int k0 = q * (HID / KSPL);           // 32 k's per quarter

    const float* Ws[6] = {W20, W11, W21, W12, W22, Wo};
    const float* bs[6] = {b20, b11, b21, b12, b22, (const float*)0};

    // issue layer-0 weight loads early (independent of everything below)
    float wc[HID / KSPL];
    #pragma unroll
    for (int kk = 0; kk < HID / KSPL; kk++) wc[kk] = Ws[0][(k0 + kk) * HID + c];

    // dmax = 2*max||x|| (triangle-inequality bound), deterministic per block
    float mx = 0.0f;
    for (int t = threadIdx.x; t < BB * NN; t += NE_THREADS) {
        float a = x[2 * t], b = x[2 * t + 1];
        mx = fmaxf(mx, fmaf(a, a, b * b));
    }
    red[threadIdx.x] = mx;
    __syncthreads();
    #pragma unroll
    for (int s = NE_THREADS / 2; s > 0; s >>= 1) {
        if (threadIdx.x < s) red[threadIdx.x] = fmaxf(red[threadIdx.x], red[threadIdx.x + s]);
        __syncthreads();
    }
    const float dmax = 2.0f * sqrtf(red[0]) * 1.000001f + 1e-6f;
    if (blockIdx.x == 0 && threadIdx.x == 0) g_inv_hd = 2.0f / dmax;

    // layer 0 (scalar input): threads 0..255 compute the 2 nodes of this block
    if (threadIdx.x < NODES * HID) {
        int n = threadIdx.x >> 7;              // 0..1
        int mnode = blockIdx.x * NODES + n;
        float d = 0.5f * (cospif((mnode + 0.5f) * (1.0f / DD)) + 1.0f) * dmax;
        float a = fmaf(d, W10[c], b10[c]);
        buf[n][c] = a / (1.0f + expf(-a));
    }
    __syncthreads();

    #pragma unroll
    for (int l = 0; l < 6; l++) {
        // prefetch next layer's weights (hides LDG latency under compute+syncs)
        float wn[HID / KSPL];
        if (l < 5) {
            #pragma unroll
            for (int kk = 0; kk < HID / KSPL; kk++)
                wn[kk] = Ws[l + 1][(k0 + kk) * HID + c];
        }
        float h0 = 0.0f, h1 = 0.0f;
        #pragma unroll
        for (int kk4 = 0; kk4 < HID / KSPL / 4; kk4++) {   // 8 iters, float4 buf reads
            const int k = k0 + 4 * kk4;
            float4 a0 = *reinterpret_cast<const float4*>(&buf[0][k]);
            float4 a1 = *reinterpret_cast<const float4*>(&buf[1][k]);
            h0 = fmaf(a0.x, wc[4 * kk4 + 0], h0);
            h1 = fmaf(a1.x, wc[4 * kk4 + 0], h1);
            h0 = fmaf(a0.y, wc[4 * kk4 + 1], h0);
            h1 = fmaf(a1.y, wc[4 * kk4 + 1], h1);
            h0 = fmaf(a0.z, wc[4 * kk4 + 2], h0);
            h1 = fmaf(a1.z, wc[4 * kk4 + 2], h1);
            h0 = fmaf(a0.w, wc[4 * kk4 + 3], h0);
            h1 = fmaf(a1.w, wc[4 * kk4 + 3], h1);
        }
        part[q][0][c] = h0;
        part[q][1][c] = h1;
        __syncthreads();
        // thread-sets q = 0,1 finalize nodes 0,1 (between the two syncs:
        // part reads done before next layer's overwrites, buf writes done
        // before next layer's reads)
        if (q < NODES) {
            float v = (bs[l] ? bs[l][c] : 0.0f) +
                      ((part[0][q][c] + part[1][q][c]) + (part[2][q][c] + part[3][q][c]));
            if (l == 1 || l == 3) v = v / (1.0f + expf(-v));   // silu after W1_1, W1_2
            if (l < 5) buf[q][c] = v;
            else g_G[(blockIdx.x * NODES + q) * HID + c] = v;
        }
        __syncthreads();
        #pragma unroll
        for (int kk = 0; kk < HID / KSPL; kk++) wc[kk] = wn[kk];
    }

    // ---- grid barrier across the 16 co-resident blocks (replay-safe) ----
    __threadfence();
    if (threadIdx.x == 0) {
        atomicAdd(&g_arrive, 1u);
        while (*(volatile unsigned*)&g_arrive < (unsigned)NE_BLOCKS) __nanosleep(32);
    }
    __syncthreads();
    __threadfence();

    // ---- phase 2: DCT-II. Block handles k = blockIdx*2 + q (q = 0,1). ----
    if (threadIdx.x < NODES * DD) {
        int qq = threadIdx.x >> 5, m = threadIdx.x & 31;
        int k = blockIdx.x * NODES + qq;
        int num = (k * (2 * m + 1)) & (4 * DD - 1);   // cospi period 2 -> mod 128
        costab[qq][m] = cospif((float)num * (1.0f / (2.0f * DD)));
    }
    for (int t = threadIdx.x; t < DD * HID / 4; t += NE_THREADS)
        reinterpret_cast<float4*>(sG)[t] =
            __ldcg(reinterpret_cast<const float4*>(g_G) + t);
    __syncthreads();

    if (q < NODES) {
        int k = blockIdx.x * NODES + q;
        float acc = 0.0f;
        #pragma unroll
        for (int m = 0; m < DD; m++) acc = fmaf(costab[q][m], sG[m][c], acc);
        float wgt = (k == 0) ? (1.0f / DD) : (2.0f / DD);
        g_C[k * HID + c] = acc * wgt;
    }

    // exit: restore barrier counter to 0 for the next graph replay
    __syncthreads();
    if (threadIdx.x == 0) atomicSub(&g_arrive, 1u);
}

// ---------------------------------------------------------------------------
// Hot kernel (R12 form): per (b,i), s[k] = sum_j T_k(z_ij); out = (1/N) s@C + bo.
// 256 blocks x 512 thr: block = 4 rows x 4 warps/row (j-split 128 each).
// ---------------------------------------------------------------------------
__global__ __launch_bounds__(512, 2) void cheb_main_kernel(
    const float* __restrict__ x, const float* __restrict__ bo,
    float* __restrict__ out)
{
    __shared__ float sx[NN * 2];
    __shared__ float sred[16][DD];         // per-warp reduced s
    __shared__ float sredc[4][DD];         // per-row combined s

    const float inv_hd = g_inv_hd;         // published by prologue

    const int b = blockIdx.x >> 7;         // 128 blocks per batch
    for (int t = threadIdx.x; t < NN * 2 / 4; t += 512)
        reinterpret_cast<float4*>(sx)[t] =
            reinterpret_cast<const float4*>(x + b * NN * 2)[t];
    __syncthreads();

    const int w    = threadIdx.x >> 5;     // warp 0..15
    const int lane = threadIdx.x & 31;
    const int r    = w >> 2;               // row-in-block 0..3
    const int h    = w & 3;                // j-quarter 0..3
    const int i    = ((blockIdx.x & 127) << 2) + r;   // row within batch
    const float xi0 = sx[2 * i], xi1 = sx[2 * i + 1];

    float s[DD];
    {
        const int j0 = h * 128;
        const int ja = j0 + lane, jb = ja + 32, jc = ja + 64, jd = ja + 96;
        float dxa = xi0 - sx[2 * ja], dya = xi1 - sx[2 * ja + 1];
        float dxb = xi0 - sx[2 * jb], dyb = xi1 - sx[2 * jb + 1];
        float dxc = xi0 - sx[2 * jc], dyc = xi1 - sx[2 * jc + 1];
        float dxd = xi0 - sx[2 * jd], dyd = xi1 - sx[2 * jd + 1];
        float za = fmaf(sqrtf(fmaf(dxa, dxa, dya * dya)), inv_hd, -1.0f);
        float zb = fmaf(sqrtf(fmaf(dxb, dxb, dyb * dyb)), inv_hd, -1.0f);
        float zc = fmaf(sqrtf(fmaf(dxc, dxc, dyc * dyc)), inv_hd, -1.0f);
        float zd = fmaf(sqrtf(fmaf(dxd, dxd, dyd * dyd)), inv_hd, -1.0f);
        za = fminf(fmaxf(za, -1.0f), 1.0f);
        zb = fminf(fmaxf(zb, -1.0f), 1.0f);
        zc = fminf(fmaxf(zc, -1.0f), 1.0f);
        zd = fminf(fmaxf(zd, -1.0f), 1.0f);

        s[0] = 4.0f;                       // T_0 == 1, 4 source nodes per lane
        s[1] = (za + zb) + (zc + zd);
        float t0a = 1.0f, t1a = za, z2a = za + za;
        float t0b = 1.0f, t1b = zb, z2b = zb + zb;
        float t0c = 1.0f, t1c = zc, z2c = zc + zc;
        float t0d = 1.0f, t1d = zd, z2d = zd + zd;
        #pragma unroll
        for (int k = 2; k < DD; k++) {
            float ta = fmaf(z2a, t1a, -t0a); t0a = t1a; t1a = ta;
            float tb = fmaf(z2b, t1b, -t0b); t0b = t1b; t1b = tb;
            float tc = fmaf(z2c, t1c, -t0c); t0c = t1c; t1c = tc;
            float td = fmaf(z2d, t1d, -t0d); t0d = t1d; t1d = td;
            s[k] = (ta + tb) + (tc + td);
        }
    }

    // reduce-scatter butterfly, explicit stage lengths: lane ends with k = lane
    #pragma unroll
    for (int st = 0; st < 5; st++) {
        const int off = 16 >> st;
        const int len = 16 >> st;
        const bool hi = (lane & off) != 0;
        #pragma unroll
        for (int k = 0; k < len; k++) {
            float send = hi ? s[k] : s[k + len];
            float recv = __shfl_xor_sync(0xffffffffu, send, off);
            s[k] = (hi ? s[k + len] : s[k]) + recv;
        }
    }
    sred[w][lane] = s[0];
    __syncthreads();

    // combine the 4 j-quarters per row (deterministic sequential order)
    if (threadIdx.x < 4 * DD) {
        const int rr = threadIdx.x >> 5, kk = threadIdx.x & 31;
        sredc[rr][kk] = ((sred[4 * rr][kk]     + sred[4 * rr + 1][kk])
                       + (sred[4 * rr + 2][kk] + sred[4 * rr + 3][kk]))
                        * (1.0f / (float)NN);
    }
    __syncthreads();

    // contract with C: warp owns 32 columns, lane owns 1 (coalesced LDG of C)
    const int c0 = h * 32 + lane;
    float acc = bo[c0];
    #pragma unroll
    for (int k = 0; k < DD; k++)
        acc = fmaf(sredc[r][k], g_C[k * HID + c0], acc);
    const int gi = b * NN + i;
    out[gi * HID + c0] = acc;
}

// ---------------------------------------------------------------------------
// Launch: 2 graph-capturable kernels.
// Input order: x, W1_0,b1_0,W2_0,b2_0, W1_1,b1_1,W2_1,b2_1, W1_2,b1_2,W2_2,b2_2, Wo,bo
// ---------------------------------------------------------------------------
extern "C" void kernel_launch(void* const* d_in, const int* in_sizes, int n_in,
                              void* d_out, int out_size)
{
    const float* x   = (const float*)d_in[0];
    const float* W10 = (const float*)d_in[1];
    const float* b10 = (const float*)d_in[2];
    const float* W20 = (const float*)d_in[3];
    const float* b20 = (const float*)d_in[4];
    const float* W11 = (const float*)d_in[5];
    const float* b11 = (const float*)d_in[6];
    const float* W21 = (const float*)d_in[7];
    const float* b21 = (const float*)d_in[8];
    const float* W12 = (const float*)d_in[9];
    const float* b12 = (const float*)d_in[10];
    const float* W22 = (const float*)d_in[11];
    const float* b22 = (const float*)d_in[12];
    const float* Wo  = (const float*)d_in[13];
    const float* bo  = (const float*)d_in[14];
    float* out = (float*)d_out;

    prologue_kernel<<<NE_BLOCKS, NE_THREADS>>>(x, W10, b10, W20, b20, W11, b11,
                                               W21, b21, W12, b12, W22, b22, Wo);
    cheb_main_kernel<<<(BB * NN) / 4, 512>>>(x, bo, out);
}

// round 15
// speedup vs baseline: 1.3252x; 1.1047x over previous
#include <cuda_runtime.h>
#include <math.h>

// Shapes (fixed by the problem)
#define BB  2
#define NN  512
#define HID 128
#define DD  32    // Chebyshev orders; measured: truncation below fp32 noise at 32

// prologue tiling: 32 blocks x 512 thr, 1 node/block, k split 16 ways
#define NE_BLOCKS DD               // 32
#define NE_THREADS 512

// Scratch (static device globals; no allocation)
__device__ float g_inv_hd;        // 2 / dmax
__device__ float g_G[DD * HID];   // network(+Wo) at Chebyshev nodes
__device__ float g_C[DD * HID];   // Chebyshev coefficients
__device__ unsigned g_arrive;     // grid barrier counter (0 at start AND end of every launch)

// ---------------------------------------------------------------------------
// Prologue: phase 1 = exact fp32 network at DD Chebyshev nodes (+Wo fold),
// phase 2 (after 32-block grid barrier) = DCT-II -> coefficients.
// Thread (kq, c4): kq = 8-k group (16 groups), c4 = 4-column group (32 groups).
// Per thread per layer: 8 LDG.128 (weights, coalesced, prefetched),
// 8 broadcast LDS (buf), 32 FMA. 32 SMs active.
// ---------------------------------------------------------------------------
__global__ __launch_bounds__(NE_THREADS) void prologue_kernel(
    const float* __restrict__ x,
    const float* __restrict__ W10, const float* __restrict__ b10,
    const float* __restrict__ W20, const float* __restrict__ b20,
    const float* __restrict__ W11, const float* __restrict__ b11,
    const float* __restrict__ W21, const float* __restrict__ b21,
    const float* __restrict__ W12, const float* __restrict__ b12,
    const float* __restrict__ W22, const float* __restrict__ b22,
    const float* __restrict__ Wo)
{
    __shared__ float red[16];
    __shared__ float sdmax;
    __shared__ __align__(16) float buf[HID];          // activations (1 node)
    __shared__ __align__(16) float part[16][HID];     // per-k-group partials (8KB)
    __shared__ float costab[DD];                      // phase 2: cos table
    __shared__ __align__(16) float sG[DD][HID];       // phase 2: staged G (16KB)

    const int tid  = threadIdx.x;
    const int kq   = tid >> 5;                 // 0..15: owns k = kq*8 .. kq*8+7
    const int c4   = tid & 31;                 // owns columns 4*c4 .. 4*c4+3
    const int lane = tid & 31;
    const int wrp  = tid >> 5;

    const float* Ws[6] = {W20, W11, W21, W12, W22, Wo};
    const float* bs[6] = {b20, b11, b21, b12, b22, (const float*)0};

    // issue layer-0 (W20) weight loads early: 8 float4 per thread
    float4 wv[8];
    #pragma unroll
    for (int kk = 0; kk < 8; kk++)
        wv[kk] = *reinterpret_cast<const float4*>(&Ws[0][(kq * 8 + kk) * HID + 4 * c4]);

    // dmax = 2*max||x||: one float4 per thread (512*4 = 2048 floats exactly),
    // warp shfl-max + tiny tree. max is order-invariant -> deterministic.
    {
        float4 v = reinterpret_cast<const float4*>(x)[tid];
        float m = fmaxf(fmaf(v.x, v.x, v.y * v.y), fmaf(v.z, v.z, v.w * v.w));
        #pragma unroll
        for (int off = 16; off > 0; off >>= 1)
            m = fmaxf(m, __shfl_xor_sync(0xffffffffu, m, off));
        if (lane == 0) red[wrp] = m;
        __syncthreads();
        if (tid == 0) {
            float mm = red[0];
            #pragma unroll
            for (int g = 1; g < 16; g++) mm = fmaxf(mm, red[g]);
            float dm = 2.0f * sqrtf(mm) * 1.000001f + 1e-6f;
            sdmax = dm;
            if (blockIdx.x == 0) g_inv_hd = 2.0f / dm;
        }
        __syncthreads();
    }
    const float dmax = sdmax;

    // layer 0 (scalar input): node = blockIdx.x
    if (tid < HID) {
        float d = 0.5f * (cospif((blockIdx.x + 0.5f) * (1.0f / DD)) + 1.0f) * dmax;
        float a = fmaf(d, W10[tid], b10[tid]);
        buf[tid] = a / (1.0f + expf(-a));
    }
    __syncthreads();

    #pragma unroll
    for (int l = 0; l < 6; l++) {
        // prefetch next layer's weights (hides LDG latency under compute+syncs)
        float4 wn[8];
        if (l < 5) {
            #pragma unroll
            for (int kk = 0; kk < 8; kk++)
                wn[kk] = *reinterpret_cast<const float4*>(&Ws[l + 1][(kq * 8 + kk) * HID + 4 * c4]);
        }
        float h0 = 0.0f, h1 = 0.0f, h2 = 0.0f, h3 = 0.0f;
        #pragma unroll
        for (int kk = 0; kk < 8; kk++) {
            const float a = buf[kq * 8 + kk];      // broadcast within warp
            h0 = fmaf(a, wv[kk].x, h0);
            h1 = fmaf(a, wv[kk].y, h1);
            h2 = fmaf(a, wv[kk].z, h2);
            h3 = fmaf(a, wv[kk].w, h3);
        }
        reinterpret_cast<float4*>(part[kq])[c4] = make_float4(h0, h1, h2, h3);
        __syncthreads();
        // finalize column c (threads 0..127), deterministic sequential combine
        if (tid < HID) {
            float v = bs[l] ? bs[l][tid] : 0.0f;
            #pragma unroll
            for (int g = 0; g < 16; g++) v += part[g][tid];
            if (l == 1 || l == 3) v = v / (1.0f + expf(-v));   // silu after W1_1, W1_2
            if (l < 5) buf[tid] = v;
            else g_G[blockIdx.x * HID + tid] = v;
        }
        __syncthreads();
        #pragma unroll
        for (int kk = 0; kk < 8; kk++) wv[kk] = wn[kk];
    }

    // ---- grid barrier across the 32 co-resident blocks (replay-safe) ----
    __threadfence();
    if (tid == 0) {
        atomicAdd(&g_arrive, 1u);
        while (*(volatile unsigned*)&g_arrive < (unsigned)NE_BLOCKS) __nanosleep(32);
    }
    __syncthreads();
    __threadfence();

    // ---- phase 2: DCT-II. Block produces coefficient row k = blockIdx. ----
    if (tid < DD) {
        int num = (blockIdx.x * (2 * tid + 1)) & (4 * DD - 1);   // cospi period 2
        costab[tid] = cospif((float)num * (1.0f / (2.0f * DD)));
    }
    for (int t = tid; t < DD * HID / 4; t += NE_THREADS)
        reinterpret_cast<float4*>(sG)[t] =
            __ldcg(reinterpret_cast<const float4*>(g_G) + t);
    __syncthreads();

    // m split 4 ways: thread (mq, c), mq = tid>>7 owns 8 m's
    {
        const int mq = tid >> 7, c = tid & (HID - 1);
        float acc = 0.0f;
        #pragma unroll
        for (int mm = 0; mm < 8; mm++) {
            const int m = mq * 8 + mm;
            acc = fmaf(costab[m], sG[m][c], acc);
        }
        part[mq][c] = acc;
    }
    __syncthreads();
    if (tid < HID) {
        float wgt = (blockIdx.x == 0) ? (1.0f / DD) : (2.0f / DD);
        float acc = (part[0][tid] + part[1][tid]) + (part[2][tid] + part[3][tid]);
        g_C[blockIdx.x * HID + tid] = acc * wgt;
    }

    // exit: restore barrier counter to 0 for the next graph replay
    __syncthreads();
    if (tid == 0) atomicSub(&g_arrive, 1u);
}

// ---------------------------------------------------------------------------
// Hot kernel (R14 form, unchanged): per (b,i), s[k] = sum_j T_k(z_ij);
// out = (1/N) s@C + bo. 256 blocks x 512 thr: 4 rows x 4 warps/row.
// ---------------------------------------------------------------------------
__global__ __launch_bounds__(512, 2) void cheb_main_kernel(
    const float* __restrict__ x, const float* __restrict__ bo,
    float* __restrict__ out)
{
    __shared__ float sx[NN * 2];
    __shared__ float sred[16][DD];         // per-warp reduced s
    __shared__ float sredc[4][DD];         // per-row combined s

    const float inv_hd = g_inv_hd;         // published by prologue

    const int b = blockIdx.x >> 7;         // 128 blocks per batch
    for (int t = threadIdx.x; t < NN * 2 / 4; t += 512)
        reinterpret_cast<float4*>(sx)[t] =
            reinterpret_cast<const float4*>(x + b * NN * 2)[t];
    __syncthreads();

    const int w    = threadIdx.x >> 5;     // warp 0..15
    const int lane = threadIdx.x & 31;
    const int r    = w >> 2;               // row-in-block 0..3
    const int h    = w & 3;                // j-quarter 0..3
    const int i    = ((blockIdx.x & 127) << 2) + r;   // row within batch
    const float xi0 = sx[2 * i], xi1 = sx[2 * i + 1];

    float s[DD];
    {
        const int j0 = h * 128;
        const int ja = j0 + lane, jb = ja + 32, jc = ja + 64, jd = ja + 96;
        float dxa = xi0 - sx[2 * ja], dya = xi1 - sx[2 * ja + 1];
        float dxb = xi0 - sx[2 * jb], dyb = xi1 - sx[2 * jb + 1];
        float dxc = xi0 - sx[2 * jc], dyc = xi1 - sx[2 * jc + 1];
        float dxd = xi0 - sx[2 * jd], dyd = xi1 - sx[2 * jd + 1];
        float za = fmaf(sqrtf(fmaf(dxa, dxa, dya * dya)), inv_hd, -1.0f);
        float zb = fmaf(sqrtf(fmaf(dxb, dxb, dyb * dyb)), inv_hd, -1.0f);
        float zc = fmaf(sqrtf(fmaf(dxc, dxc, dyc * dyc)), inv_hd, -1.0f);
        float zd = fmaf(sqrtf(fmaf(dxd, dxd, dyd * dyd)), inv_hd, -1.0f);
        za = fminf(fmaxf(za, -1.0f), 1.0f);
        zb = fminf(fmaxf(zb, -1.0f), 1.0f);
        zc = fminf(fmaxf(zc, -1.0f), 1.0f);
        zd = fminf(fmaxf(zd, -1.0f), 1.0f);

        s[0] = 4.0f;                       // T_0 == 1, 4 source nodes per lane
        s[1] = (za + zb) + (zc + zd);
        float t0a = 1.0f, t1a = za, z2a = za + za;
        float t0b = 1.0f, t1b = zb, z2b = zb + zb;
        float t0c = 1.0f, t1c = zc, z2c = zc + zc;
        float t0d = 1.0f, t1d = zd, z2d = zd + zd;
        #pragma unroll
        for (int k = 2; k < DD; k++) {
            float ta = fmaf(z2a, t1a, -t0a); t0a = t1a; t1a = ta;
            float tb = fmaf(z2b, t1b, -t0b); t0b = t1b; t1b = tb;
            float tc = fmaf(z2c, t1c, -t0c); t0c = t1c; t1c = tc;
            float td = fmaf(z2d, t1d, -t0d); t0d = t1d; t1d = td;
            s[k] = (ta + tb) + (tc + td);
        }
    }

    // reduce-scatter butterfly, explicit stage lengths: lane ends with k = lane
    #pragma unroll
    for (int st = 0; st < 5; st++) {
        const int off = 16 >> st;
        const int len = 16 >> st;
        const bool hi = (lane & off) != 0;
        #pragma unroll
        for (int k = 0; k < len; k++) {
            float send = hi ? s[k] : s[k + len];
            float recv = __shfl_xor_sync(0xffffffffu, send, off);
            s[k] = (hi ? s[k + len] : s[k]) + recv;
        }
    }
    sred[w][lane] = s[0];
    __syncthreads();

    // combine the 4 j-quarters per row (deterministic sequential order)
    if (threadIdx.x < 4 * DD) {
        const int rr = threadIdx.x >> 5, kk = threadIdx.x & 31;
        sredc[rr][kk] = ((sred[4 * rr][kk]     + sred[4 * rr + 1][kk])
                       + (sred[4 * rr + 2][kk] + sred[4 * rr + 3][kk]))
                        * (1.0f / (float)NN);
    }
    __syncthreads();

    // contract with C: warp owns 32 columns, lane owns 1 (coalesced LDG of C)
    const int c0 = h * 32 + lane;
    float acc = bo[c0];
    #pragma unroll
    for (int k = 0; k < DD; k++)
        acc = fmaf(sredc[r][k], g_C[k * HID + c0], acc);
    const int gi = b * NN + i;
    out[gi * HID + c0] = acc;
}

// ---------------------------------------------------------------------------
// Launch: 2 graph-capturable kernels.
// Input order: x, W1_0,b1_0,W2_0,b2_0, W1_1,b1_1,W2_1,b2_1, W1_2,b1_2,W2_2,b2_2, Wo,bo
// ---------------------------------------------------------------------------
extern "C" void kernel_launch(void* const* d_in, const int* in_sizes, int n_in,
                              void* d_out, int out_size)
{
    const float* x   = (const float*)d_in[0];
    const float* W10 = (const float*)d_in[1];
    const float* b10 = (const float*)d_in[2];
    const float* W20 = (const float*)d_in[3];
    const float* b20 = (const float*)d_in[4];
    const float* W11 = (const float*)d_in[5];
    const float* b11 = (const float*)d_in[6];
    const float* W21 = (const float*)d_in[7];
    const float* b21 = (const float*)d_in[8];
    const float* W12 = (const float*)d_in[9];
    const float* b12 = (const float*)d_in[10];
    const float* W22 = (const float*)d_in[11];
    const float* b22 = (const float*)d_in[12];
    const float* Wo  = (const float*)d_in[13];
    const float* bo  = (const float*)d_in[14];
    float* out = (float*)d_out;

    prologue_kernel<<<NE_BLOCKS, NE_THREADS>>>(x, W10, b10, W20, b20, W11, b11,
                                               W21, b21, W12, b12, W22, b22, Wo);
    cheb_main_kernel<<<(BB * NN) / 4, 512>>>(x, bo, out);
}